// round 15
// baseline (speedup 1.0000x reference)
#include <cuda_runtime.h>
#include <cuda_fp16.h>
#include <cmath>

// Problem constants
#define LSTEPS 47
#define RR 24
#define OO 24
#define BB 64
#define EMB 128
#define HH 256
#define M1 1536        // RR * BB
#define MALL 72192     // LSTEPS * M1

#define OUT_ALL_ELEMS 36962304   // M1 * LSTEPS * 512
#define HID_ELEMS 393216         // BB * 24 * HH

// Scratch
__device__ __half d_xy[(size_t)MALL * 256];   // [x | y] packed fp16
__device__ __half d_qkv[(size_t)MALL * 384];  // fp16 qkv
__device__ __half d_att[(size_t)MALL * 128];
__device__ __half d_pre[(size_t)MALL * 1536]; // fp16 gate pre-activations
__device__ __half d_ht[2 * M1 * 512];         // fp16 state ping-pong [h_row|h_col]
__device__ __half d_g[2 * (size_t)M1 * 1536]; // fp16 split-K partial sums
__device__ __half d_Wt[1536 * 768];
__device__ __half d_inwt[384 * 128];
__device__ __half d_outwt[128 * 128];

__device__ __forceinline__ float tanha(float x) {
    float y; asm("tanh.approx.f32 %0, %1;" : "=f"(y) : "f"(x)); return y;
}
__device__ __forceinline__ float sigf(float x) { return 1.f / (1.f + __expf(-x)); }

// ---------------------------------------------------------------------------
// Fused one-time weight conversion (float -> half)
// ---------------------------------------------------------------------------
#define W4   294912
#define IW4  12288
#define OW4  4096
__global__ void cvt_all_kernel(const float* __restrict__ W, __half* __restrict__ Wt,
                               const float* __restrict__ inw, __half* __restrict__ inwt,
                               const float* __restrict__ outw, __half* __restrict__ outwt) {
    int i = blockIdx.x * 256 + threadIdx.x;
    const float4* src; __half2* dst; int j;
    if (i < W4) {
        src = (const float4*)W; dst = (__half2*)Wt; j = i;
    } else if (i < W4 + IW4) {
        src = (const float4*)inw; dst = (__half2*)inwt; j = i - W4;
    } else if (i < W4 + IW4 + OW4) {
        src = (const float4*)outw; dst = (__half2*)outwt; j = i - W4 - IW4;
    } else return;
    float4 v = src[j];
    dst[j * 2]     = __floats2half2_rn(v.x, v.y);
    dst[j * 2 + 1] = __floats2half2_rn(v.z, v.w);
}

// ---------------------------------------------------------------------------
// build x (fp16): xy[m*256 + i] = input[b, l-r, r, i] (zero outside)
// ---------------------------------------------------------------------------
__global__ void build_x_kernel(const float* __restrict__ input, __half* __restrict__ xy) {
    int idx = blockIdx.x * 256 + threadIdx.x;
    if (idx >= MALL * 32) return;
    int c = idx & 31;
    int m = idx >> 5;
    int b = m & 63;
    int t = m >> 6;
    int r = t % RR;
    int l = t / RR;
    int o = l - r;
    __half2 h0 = __floats2half2_rn(0.f, 0.f), h1 = h0;
    if (o >= 0 && o < OO) {
        float4 v = ((const float4*)(input + (size_t)((b * OO + o) * RR + r) * EMB))[c];
        h0 = __floats2half2_rn(v.x, v.y);
        h1 = __floats2half2_rn(v.z, v.w);
    }
    __half2* p = (__half2*)(xy + (size_t)m * 256) + c * 2;
    p[0] = h0; p[1] = h1;
}

// ---------------------------------------------------------------------------
// MMA / cp.async primitives
// ---------------------------------------------------------------------------
__device__ __forceinline__ void mma_f16(float* d, const unsigned* a, const unsigned* b) {
    asm volatile(
        "mma.sync.aligned.m16n8k16.row.col.f32.f16.f16.f32 "
        "{%0,%1,%2,%3}, {%4,%5,%6,%7}, {%8,%9}, {%0,%1,%2,%3};\n"
        : "+f"(d[0]), "+f"(d[1]), "+f"(d[2]), "+f"(d[3])
        : "r"(a[0]), "r"(a[1]), "r"(a[2]), "r"(a[3]), "r"(b[0]), "r"(b[1]));
}
__device__ __forceinline__ void cpasync16(void* dst, const void* src) {
    unsigned saddr = (unsigned)__cvta_generic_to_shared(dst);
    asm volatile("cp.async.cg.shared.global [%0], [%1], 16;\n" :: "r"(saddr), "l"(src));
}

// ===========================================================================
// FP16 MMA GEMM (128x128 tile, BK=32 halves, 4-stage cp.async).
// C = A @ Bwᵀ (+Cinit fp32|fp16)(+bias). out_half selects fp16 C.
// ksplit: grid.z slices K; slice z writes C + z*M1*ldc (element units of C's
// type), Cinit only z=0.
// ===========================================================================
#define STAGE_U 4096   // uints per stage (A 2048 + B 2048) = 16KB

__global__ __launch_bounds__(256, 2)
void gemm_mma(const __half* __restrict__ A, int lda,
              const __half* __restrict__ Bw, int ldb,
              const float* __restrict__ bias,
              const void* __restrict__ Cinit, int cinit_half,
              float* __restrict__ C, int ldc, int K, int out_half, int ksplit)
{
    cudaGridDependencySynchronize();
    extern __shared__ unsigned sm[];
    int kh = blockIdx.z;
    if (kh) {
        A += kh * ksplit;
        Bw += kh * ksplit;
        if (out_half) C = (float*)((__half*)C + (size_t)kh * M1 * ldc);
        else          C = C + (size_t)kh * M1 * ldc;
        Cinit = nullptr;
    }
    int tid  = threadIdx.x;
    int lane = tid & 31;
    int warp = tid >> 5;
    int wm = (warp >> 2) * 64;
    int wn = (warp & 3) * 32;
    int g  = lane >> 2;
    int tg = lane & 3;
    int m0 = blockIdx.y * 128;
    int n0 = blockIdx.x * 128;

    int prow = tid >> 2;
    int pch  = (tid & 3) << 2;
    int psw  = ((prow >> 1) & 3) << 2;
    int dA   = prow * 16 + (pch ^ psw);
    const __half* Ag   = A  + (size_t)(m0 + prow) * lda + pch * 2;
    const __half* Ag64 = Ag + (size_t)64 * lda;
    const __half* Bg   = Bw + (size_t)(n0 + prow) * ldb + pch * 2;
    const __half* Bg64 = Bg + (size_t)64 * ldb;

    auto prefetch = [&](int st, int k0) {
        unsigned* sA = sm + st * STAGE_U;
        unsigned* sB = sA + 2048;
        cpasync16(sA + dA,        Ag   + k0);
        cpasync16(sA + dA + 1024, Ag64 + k0);
        cpasync16(sB + dA,        Bg   + k0);
        cpasync16(sB + dA + 1024, Bg64 + k0);
        asm volatile("cp.async.commit_group;\n" ::);
    };

    float acc[4][4][4];
#pragma unroll
    for (int i = 0; i < 4; ++i)
#pragma unroll
        for (int j = 0; j < 4; ++j)
#pragma unroll
            for (int q = 0; q < 4; ++q) acc[i][j][q] = 0.f;

    int ktiles = K >> 5;
    prefetch(0, 0); prefetch(1, 32); prefetch(2, 64);
    int swz = ((g >> 1) & 3) << 2;

    for (int kt = 0; kt < ktiles; ++kt) {
        asm volatile("cp.async.wait_group 2;\n" ::);
        __syncthreads();
        if (kt + 3 < ktiles) prefetch((kt + 3) & 3, (kt + 3) << 5);
        else asm volatile("cp.async.commit_group;\n" ::);

        const unsigned* sA = sm + (kt & 3) * STAGE_U;
        const unsigned* sB = sA + 2048;
        const unsigned* pA = sA + (wm + g) * 16;
        const unsigned* pB = sB + (wn + g) * 16;

#pragma unroll
        for (int ks = 0; ks < 2; ++ks) {
            int c0 = (ks * 8 + tg) ^ swz;
            int c4 = (ks * 8 + tg + 4) ^ swz;
            unsigned af[4][4], bf[4][2];
#pragma unroll
            for (int i = 0; i < 4; ++i) {
                af[i][0] = pA[i * 256 + c0];
                af[i][1] = pA[i * 256 + 128 + c0];
                af[i][2] = pA[i * 256 + c4];
                af[i][3] = pA[i * 256 + 128 + c4];
            }
#pragma unroll
            for (int j = 0; j < 4; ++j) {
                bf[j][0] = pB[j * 128 + c0];
                bf[j][1] = pB[j * 128 + c4];
            }
#pragma unroll
            for (int i = 0; i < 4; ++i)
#pragma unroll
                for (int j = 0; j < 4; ++j)
                    mma_f16(acc[i][j], af[i], bf[j]);
        }
    }

#pragma unroll
    for (int i = 0; i < 4; ++i) {
        int r0 = m0 + wm + i * 16 + g;
#pragma unroll
        for (int j = 0; j < 4; ++j) {
            int c = n0 + wn + j * 8 + 2 * tg;
            float v0 = acc[i][j][0], v1 = acc[i][j][1];
            float v2 = acc[i][j][2], v3 = acc[i][j][3];
            if (Cinit) {
                if (cinit_half) {
                    const __half* Ch = (const __half*)Cinit;
                    float2 p0 = __half22float2(*(const __half2*)&Ch[(size_t)r0 * ldc + c]);
                    float2 p1 = __half22float2(*(const __half2*)&Ch[(size_t)(r0 + 8) * ldc + c]);
                    v0 += p0.x; v1 += p0.y; v2 += p1.x; v3 += p1.y;
                } else {
                    const float* Cf = (const float*)Cinit;
                    float2 p0 = *(const float2*)&Cf[(size_t)r0 * ldc + c];
                    float2 p1 = *(const float2*)&Cf[(size_t)(r0 + 8) * ldc + c];
                    v0 += p0.x; v1 += p0.y; v2 += p1.x; v3 += p1.y;
                }
            }
            if (bias) {
                float2 bb = *(const float2*)&bias[c];
                v0 += bb.x; v1 += bb.y; v2 += bb.x; v3 += bb.y;
            }
            if (out_half) {
                __half* Ch = (__half*)C;
                *(__half2*)&Ch[(size_t)r0 * ldc + c]       = __floats2half2_rn(v0, v1);
                *(__half2*)&Ch[(size_t)(r0 + 8) * ldc + c] = __floats2half2_rn(v2, v3);
            } else {
                *(float2*)&C[(size_t)r0 * ldc + c]       = make_float2(v0, v1);
                *(float2*)&C[(size_t)(r0 + 8) * ldc + c] = make_float2(v2, v3);
            }
        }
    }
}

// ---------------------------------------------------------------------------
// MHA core per (l, b): both heads per block. fp16 smem (raw copy loader),
// row stride 68 half2 = 272B (16B aligned; 272 mod 128 = 16 -> LDS.128
// conflict-free across lanes). PV reads half2 (conflict-free 4B).
// ---------------------------------------------------------------------------
#define AH2 68   // row stride in half2 units (272 bytes)

__global__ __launch_bounds__(768)
void attn_kernel(const __half* __restrict__ qkv, const float* __restrict__ mask,
                 __half* __restrict__ att) {
    cudaGridDependencySynchronize();
    int bid = blockIdx.x;
    int b = bid & 63;
    int l = bid >> 6;

    __shared__ __align__(16) __half2 qs[RR * AH2];
    __shared__ __align__(16) __half2 ks[32 * AH2];   // rows 24..31 zeroed
    __shared__ __align__(16) __half2 vs[RR * AH2];
    __shared__ float ps[RR * 32];

    int tid = threadIdx.x;
    // raw copy: 24 rows x 48 float4 (each = 4 half2); no conversion
    for (int idx = tid; idx < RR * 48; idx += 768) {
        int s = idx / 48;
        int u = idx % 48;
        float4 raw = ((const float4*)(qkv + ((size_t)(l * RR + s) * BB + b) * 384))[u];
        int seg = u >> 4;              // 0=q, 1=k, 2=v
        int w4 = (u & 15) * 4;         // half2 offset within row (16B units)
        __half2* dst = (seg == 0) ? &qs[s * AH2 + w4]
                     : (seg == 1) ? &ks[s * AH2 + w4]
                                  : &vs[s * AH2 + w4];
        *(float4*)dst = raw;
    }
    for (int idx = tid; idx < 8 * 17; idx += 768) {   // zero ks pad rows (17 float4/row)
        int s = RR + idx / 17, u = (idx % 17) * 4;
        *(float4*)&ks[s * AH2 + u] = make_float4(0.f, 0.f, 0.f, 0.f);
    }
    __syncthreads();

    int w = tid >> 5, lane = tid & 31;
    if (w >= RR) return;
    int r = w;
    float mk = (lane < RR) ? mask[r * RR + lane] : 0.f;

#pragma unroll
    for (int h = 0; h < 2; ++h) {
        int hb = h * 32;   // half2 offset of head within row
        // scores: lane j computes q[r]·k[j] over 64 dims (8 LDS.128 each side)
        float a0 = 0.f, a1 = 0.f, a2 = 0.f, a3 = 0.f;
#pragma unroll
        for (int d8 = 0; d8 < 8; ++d8) {
            float4 qraw = *(const float4*)&qs[r * AH2 + hb + d8 * 4];
            float4 kraw = *(const float4*)&ks[lane * AH2 + hb + d8 * 4];
            const __half2* qh = (const __half2*)&qraw;
            const __half2* kh = (const __half2*)&kraw;
#pragma unroll
            for (int t = 0; t < 4; ++t) {
                float2 qf = __half22float2(qh[t]);
                float2 kf = __half22float2(kh[t]);
                a0 = fmaf(qf.x, kf.x, a0);
                a1 = fmaf(qf.y, kf.y, a1);
                a2 = fmaf(qf.x, kf.x, 0.f) * 0.f + a2;  // keep 2-acc pattern minimal
                (void)a3;
            }
        }
        float sc = a0 + a1;
        float sco = (lane < RR) ? sc * 0.125f + mk : -INFINITY;

        float mx = sco;
#pragma unroll
        for (int off = 16; off; off >>= 1)
            mx = fmaxf(mx, __shfl_xor_sync(0xffffffffu, mx, off));
        float e = __expf(sco - mx);
        float sum = e;
#pragma unroll
        for (int off = 16; off; off >>= 1)
            sum += __shfl_xor_sync(0xffffffffu, sum, off);
        ps[r * 32 + lane] = e / sum;
        __syncwarp();

        // PV: lane handles dims (2*lane, 2*lane+1) via one half2 per step
        float acc0 = 0.f, acc1 = 0.f;
#pragma unroll
        for (int s = 0; s < RR; ++s) {
            float p = ps[r * 32 + s];
            float2 v01 = __half22float2(vs[s * AH2 + hb + lane]);
            acc0 = fmaf(p, v01.x, acc0);
            acc1 = fmaf(p, v01.y, acc1);
        }
        int mo = ((l * RR + r) * BB + b) * EMB + h * 64;
        *(__half2*)&att[mo + 2 * lane] = __floats2half2_rn(acc0, acc1);
        __syncwarp();
    }
}

// ---------------------------------------------------------------------------
// Gate / state update / outputs. g, g2 fp16 (g2 optional split-K partial).
// Grid-stride over 98304 items; launch with 144 blocks (one wave).
// ---------------------------------------------------------------------------
__global__ __launch_bounds__(256)
void gate_kernel(const __half* __restrict__ g,
                 const __half* __restrict__ g2,
                 const __half* __restrict__ hin,
                 __half* __restrict__ hout,
                 const float* __restrict__ Bias,
                 float* __restrict__ out_all,
                 float* __restrict__ out_col,
                 float* __restrict__ out_row,
                 int s) {
    cudaGridDependencySynchronize();
    int stride = gridDim.x * 256;
    for (int idx = blockIdx.x * 256 + threadIdx.x; idx < M1 * 64; idx += stride) {
        int c = idx & 63;
        int m = idx >> 6;
        int b = m & 63;
        int r = m >> 6;

        float4 q[6];
        {
            const __half2* Gh = (const __half2*)(g + (size_t)m * 1536);
#pragma unroll
            for (int t = 0; t < 6; ++t) {
                float2 a = __half22float2(Gh[t * 128 + 2 * c]);
                float2 bb = __half22float2(Gh[t * 128 + 2 * c + 1]);
                q[t] = make_float4(a.x, a.y, bb.x, bb.y);
            }
        }
        if (g2) {
            const __half2* Gh = (const __half2*)(g2 + (size_t)m * 1536);
#pragma unroll
            for (int t = 0; t < 6; ++t) {
                float2 a = __half22float2(Gh[t * 128 + 2 * c]);
                float2 bb = __half22float2(Gh[t * 128 + 2 * c + 1]);
                q[t].x += a.x; q[t].y += a.y; q[t].z += bb.x; q[t].w += bb.y;
            }
        }
        if (r <= s && s < RR) {
            const float4* B4 = (const float4*)Bias;
#pragma unroll
            for (int t = 0; t < 6; ++t) {
                float4 bb = B4[c + t * 64];
                q[t].x += bb.x; q[t].y += bb.y; q[t].z += bb.z; q[t].w += bb.w;
            }
        }
        float* qa = (float*)q;

        const __half2* HR = (const __half2*)(hin + (size_t)m * 512) + c * 2;
        const __half2* HC = (const __half2*)(hin + (size_t)m * 512 + 256) + c * 2;
        float2 hr01 = __half22float2(HR[0]);
        float2 hr23 = __half22float2(HR[1]);
        float2 hc01 = __half22float2(HC[0]);
        float2 hc23 = __half22float2(HC[1]);
        float hrp[4] = {hr01.x, hr01.y, hr23.x, hr23.y};
        float hcp[4] = {hc01.x, hc01.y, hc23.x, hc23.y};

        float hr[4], hc[4];
#pragma unroll
        for (int t = 0; t < 4; ++t) {
            float ug_r = sigf(qa[t]);
            float og_r = sigf(qa[4 + t]);
            float ug_c = sigf(qa[8 + t]);
            float og_c = sigf(qa[12 + t]);
            float ig_r = tanha(qa[16 + t]);
            float ig_c = tanha(qa[20 + t]);
            hr[t] = tanha((1.f - ug_r) * hrp[t] + ug_r * ig_r) * og_r;
            hc[t] = tanha((1.f - ug_c) * hcp[t] + ug_c * ig_c) * og_c;
        }
        float4 hr4 = make_float4(hr[0], hr[1], hr[2], hr[3]);
        float4 hc4 = make_float4(hc[0], hc[1], hc[2], hc[3]);

        int r2 = (r + 1) % RR;
        int mc = r2 * BB + b;
        __half2* OR = (__half2*)(hout + (size_t)m * 512) + c * 2;
        __half2* OC = (__half2*)(hout + (size_t)mc * 512 + 256) + c * 2;
        OR[0] = __floats2half2_rn(hr[0], hr[1]);
        OR[1] = __floats2half2_rn(hr[2], hr[3]);
        OC[0] = __floats2half2_rn(hc[0], hc[1]);
        OC[1] = __floats2half2_rn(hc[2], hc[3]);

        float* ob = out_all + ((size_t)m * LSTEPS + s) * 512;
        __stcs((float4*)ob + c, hr4);
        __stcs((float4*)(ob + 256) + c, hc4);

        if (s >= OO - 1) {
            int t2 = s - (OO - 1);
            if (r == t2)      ((float4*)(out_row + (size_t)(b * RR + t2) * HH))[c] = hr4;
            if (r == RR - 1)  ((float4*)(out_col + (size_t)(b * OO + t2) * HH))[c] = hc4;
        }
    }
}

// ---------------------------------------------------------------------------
// Launch
// ---------------------------------------------------------------------------
extern "C" void kernel_launch(void* const* d_in, const int* in_sizes, int n_in,
                              void* d_out, int out_size) {
    const float* input = (const float*)d_in[0];
    const float* mask  = (const float*)d_in[1];
    const float* W     = (const float*)d_in[2];
    const float* Bias  = (const float*)d_in[3];
    const float* inw   = (const float*)d_in[4];
    const float* inb   = (const float*)d_in[5];
    const float* outw  = (const float*)d_in[6];
    const float* outb  = (const float*)d_in[7];
    float* out = (float*)d_out;

    __half *xy, *qkv, *att, *pre, *ht, *g, *Wt, *inwt, *outwt;
    cudaGetSymbolAddress((void**)&xy,    d_xy);
    cudaGetSymbolAddress((void**)&qkv,   d_qkv);
    cudaGetSymbolAddress((void**)&att,   d_att);
    cudaGetSymbolAddress((void**)&pre,   d_pre);
    cudaGetSymbolAddress((void**)&ht,    d_ht);
    cudaGetSymbolAddress((void**)&g,     d_g);
    cudaGetSymbolAddress((void**)&Wt,    d_Wt);
    cudaGetSymbolAddress((void**)&inwt,  d_inwt);
    cudaGetSymbolAddress((void**)&outwt, d_outwt);

    cudaFuncSetAttribute(gemm_mma, cudaFuncAttributeMaxDynamicSharedMemorySize, 65536);
    const int SMEMB = 65536;

    // 0) one-time weight conversion to fp16
    cvt_all_kernel<<<(W4 + IW4 + OW4 + 255) / 256, 256>>>(W, Wt, inw, inwt, outw, outwt);

    // 1) x (fp16)
    build_x_kernel<<<(MALL * 32 + 255) / 256, 256>>>(input, xy);

    // 2) qkv = x @ in_proj_wᵀ + b  (fp16 out)
    gemm_mma<<<dim3(3, MALL / 128), 256, SMEMB>>>(xy, 256, inwt, EMB, inb,
                                                  nullptr, 0,
                                                  (float*)qkv, 384, EMB, 1, 0);

    // 3) attention (fp16 in/out, both heads per block)
    attn_kernel<<<LSTEPS * BB, 768>>>(qkv, mask, att);

    // 4) y = att @ out_proj_wᵀ + b -> xy[:,128:256] (fp16 out)
    gemm_mma<<<dim3(1, MALL / 128), 256, SMEMB>>>(att, EMB, outwt, EMB, outb,
                                                  nullptr, 0,
                                                  (float*)(xy + 128), 256, EMB, 1, 0);

    // 5) pre = [x|y] @ W[:, 512:768]ᵀ (fp16 out)
    gemm_mma<<<dim3(12, MALL / 128), 256, SMEMB>>>(xy, 256, Wt + 512, 768, nullptr,
                                                   nullptr, 0,
                                                   (float*)pre, 1536, 256, 1, 0);

    // 6) zero initial state (buffer 0)
    cudaMemsetAsync(ht, 0, (size_t)M1 * 512 * sizeof(__half));

    // PDL launch configs for the scan loop
    cudaLaunchAttribute pdlAttr[1];
    pdlAttr[0].id = cudaLaunchAttributeProgrammaticStreamSerialization;
    pdlAttr[0].val.programmaticStreamSerializationAllowed = 1;

    cudaLaunchConfig_t cfgGemm = {};
    cfgGemm.gridDim  = dim3(12, 12, 2);      // split-K = 2
    cfgGemm.blockDim = dim3(256);
    cfgGemm.dynamicSmemBytes = SMEMB;
    cfgGemm.stream = 0;
    cfgGemm.attrs = pdlAttr;
    cfgGemm.numAttrs = 1;

    cudaLaunchConfig_t cfgGate = {};
    cfgGate.gridDim  = dim3(144);            // one balanced wave
    cfgGate.blockDim = dim3(256);
    cfgGate.dynamicSmemBytes = 0;
    cfgGate.stream = 0;
    cfgGate.attrs = pdlAttr;
    cfgGate.numAttrs = 1;

    float* out_col = out + OUT_ALL_ELEMS;
    float* out_row = out + OUT_ALL_ELEMS + HID_ELEMS;
    __half* g1 = g + (size_t)M1 * 1536;

    // 7) sequential scan; s=0 skips the GEMM (h == 0 -> g == pre[0], fp16)
    gate_kernel<<<144, 256>>>(pre, (const __half*)nullptr, ht,
                              ht + (size_t)M1 * 512, Bias,
                              out, out_col, out_row, 0);
    for (int s = 1; s < LSTEPS; ++s) {
        const __half* hin = ht + (size_t)(s & 1) * M1 * 512;
        __half* hout      = ht + (size_t)((s + 1) & 1) * M1 * 512;
        cudaLaunchKernelEx(&cfgGemm, gemm_mma,
                           hin, 512, (const __half*)Wt, 768,
                           (const float*)nullptr,
                           (const void*)(pre + (size_t)s * M1 * 1536), 1,
                           (float*)g, 1536, 256, 1, 256);
        cudaLaunchKernelEx(&cfgGate, gate_kernel,
                           (const __half*)g, (const __half*)g1, hin, hout,
                           Bias, out, out_col, out_row, s);
    }
}

// round 16
// speedup vs baseline: 1.1546x; 1.1546x over previous
#include <cuda_runtime.h>
#include <cuda_fp16.h>
#include <cmath>

// Problem constants
#define LSTEPS 47
#define RR 24
#define OO 24
#define BB 64
#define EMB 128
#define HH 256
#define M1 1536        // RR * BB
#define MALL 72192     // LSTEPS * M1

#define OUT_ALL_ELEMS 36962304   // M1 * LSTEPS * 512
#define HID_ELEMS 393216         // BB * 24 * HH

// Scratch
__device__ __half d_xy[(size_t)MALL * 256];   // [x | y] packed fp16
__device__ __half d_qkv[(size_t)MALL * 384];  // fp16 qkv
__device__ __half d_att[(size_t)MALL * 128];
__device__ __half d_pre[(size_t)MALL * 1536]; // fp16 gate pre-activations
__device__ __half d_ht[2 * M1 * 512];         // fp16 state ping-pong [h_row|h_col]
__device__ __half d_g[2 * (size_t)M1 * 1536]; // fp16 split-K partial sums
__device__ __half d_Wt[1536 * 768];
__device__ __half d_inwt[384 * 128];
__device__ __half d_outwt[128 * 128];

__device__ __forceinline__ float tanha(float x) {
    float y; asm("tanh.approx.f32 %0, %1;" : "=f"(y) : "f"(x)); return y;
}
__device__ __forceinline__ float sigf(float x) { return 1.f / (1.f + __expf(-x)); }

// ---------------------------------------------------------------------------
// Fused one-time weight conversion (float -> half)
// ---------------------------------------------------------------------------
#define W4   294912
#define IW4  12288
#define OW4  4096
__global__ void cvt_all_kernel(const float* __restrict__ W, __half* __restrict__ Wt,
                               const float* __restrict__ inw, __half* __restrict__ inwt,
                               const float* __restrict__ outw, __half* __restrict__ outwt) {
    int i = blockIdx.x * 256 + threadIdx.x;
    const float4* src; __half2* dst; int j;
    if (i < W4) {
        src = (const float4*)W; dst = (__half2*)Wt; j = i;
    } else if (i < W4 + IW4) {
        src = (const float4*)inw; dst = (__half2*)inwt; j = i - W4;
    } else if (i < W4 + IW4 + OW4) {
        src = (const float4*)outw; dst = (__half2*)outwt; j = i - W4 - IW4;
    } else return;
    float4 v = src[j];
    dst[j * 2]     = __floats2half2_rn(v.x, v.y);
    dst[j * 2 + 1] = __floats2half2_rn(v.z, v.w);
}

// ---------------------------------------------------------------------------
// build x (fp16): xy[m*256 + i] = input[b, l-r, r, i] (zero outside)
// ---------------------------------------------------------------------------
__global__ void build_x_kernel(const float* __restrict__ input, __half* __restrict__ xy) {
    int idx = blockIdx.x * 256 + threadIdx.x;
    if (idx >= MALL * 32) return;
    int c = idx & 31;
    int m = idx >> 5;
    int b = m & 63;
    int t = m >> 6;
    int r = t % RR;
    int l = t / RR;
    int o = l - r;
    __half2 h0 = __floats2half2_rn(0.f, 0.f), h1 = h0;
    if (o >= 0 && o < OO) {
        float4 v = ((const float4*)(input + (size_t)((b * OO + o) * RR + r) * EMB))[c];
        h0 = __floats2half2_rn(v.x, v.y);
        h1 = __floats2half2_rn(v.z, v.w);
    }
    __half2* p = (__half2*)(xy + (size_t)m * 256) + c * 2;
    p[0] = h0; p[1] = h1;
}

// ---------------------------------------------------------------------------
// MMA / cp.async primitives
// ---------------------------------------------------------------------------
__device__ __forceinline__ void mma_f16(float* d, const unsigned* a, const unsigned* b) {
    asm volatile(
        "mma.sync.aligned.m16n8k16.row.col.f32.f16.f16.f32 "
        "{%0,%1,%2,%3}, {%4,%5,%6,%7}, {%8,%9}, {%0,%1,%2,%3};\n"
        : "+f"(d[0]), "+f"(d[1]), "+f"(d[2]), "+f"(d[3])
        : "r"(a[0]), "r"(a[1]), "r"(a[2]), "r"(a[3]), "r"(b[0]), "r"(b[1]));
}
__device__ __forceinline__ void cpasync16(void* dst, const void* src) {
    unsigned saddr = (unsigned)__cvta_generic_to_shared(dst);
    asm volatile("cp.async.cg.shared.global [%0], [%1], 16;\n" :: "r"(saddr), "l"(src));
}

// ===========================================================================
// FP16 MMA GEMM (128x128 tile, BK=32 halves, 4-stage cp.async).
// C = A @ Bwᵀ (+Cinit fp32|fp16)(+bias). out_half selects fp16 C.
// ksplit: grid.z slices K; slice z writes C + z*M1*ldc (element units of C's
// type), Cinit only z=0.
// ===========================================================================
#define STAGE_U 4096   // uints per stage (A 2048 + B 2048) = 16KB

__global__ __launch_bounds__(256, 2)
void gemm_mma(const __half* __restrict__ A, int lda,
              const __half* __restrict__ Bw, int ldb,
              const float* __restrict__ bias,
              const void* __restrict__ Cinit, int cinit_half,
              float* __restrict__ C, int ldc, int K, int out_half, int ksplit)
{
    cudaGridDependencySynchronize();
    extern __shared__ unsigned sm[];
    int kh = blockIdx.z;
    if (kh) {
        A += kh * ksplit;
        Bw += kh * ksplit;
        if (out_half) C = (float*)((__half*)C + (size_t)kh * M1 * ldc);
        else          C = C + (size_t)kh * M1 * ldc;
        Cinit = nullptr;
    }
    int tid  = threadIdx.x;
    int lane = tid & 31;
    int warp = tid >> 5;
    int wm = (warp >> 2) * 64;
    int wn = (warp & 3) * 32;
    int g  = lane >> 2;
    int tg = lane & 3;
    int m0 = blockIdx.y * 128;
    int n0 = blockIdx.x * 128;

    int prow = tid >> 2;
    int pch  = (tid & 3) << 2;
    int psw  = ((prow >> 1) & 3) << 2;
    int dA   = prow * 16 + (pch ^ psw);
    const __half* Ag   = A  + (size_t)(m0 + prow) * lda + pch * 2;
    const __half* Ag64 = Ag + (size_t)64 * lda;
    const __half* Bg   = Bw + (size_t)(n0 + prow) * ldb + pch * 2;
    const __half* Bg64 = Bg + (size_t)64 * ldb;

    auto prefetch = [&](int st, int k0) {
        unsigned* sA = sm + st * STAGE_U;
        unsigned* sB = sA + 2048;
        cpasync16(sA + dA,        Ag   + k0);
        cpasync16(sA + dA + 1024, Ag64 + k0);
        cpasync16(sB + dA,        Bg   + k0);
        cpasync16(sB + dA + 1024, Bg64 + k0);
        asm volatile("cp.async.commit_group;\n" ::);
    };

    float acc[4][4][4];
#pragma unroll
    for (int i = 0; i < 4; ++i)
#pragma unroll
        for (int j = 0; j < 4; ++j)
#pragma unroll
            for (int q = 0; q < 4; ++q) acc[i][j][q] = 0.f;

    int ktiles = K >> 5;
    prefetch(0, 0); prefetch(1, 32); prefetch(2, 64);
    int swz = ((g >> 1) & 3) << 2;

    for (int kt = 0; kt < ktiles; ++kt) {
        asm volatile("cp.async.wait_group 2;\n" ::);
        __syncthreads();
        if (kt + 3 < ktiles) prefetch((kt + 3) & 3, (kt + 3) << 5);
        else asm volatile("cp.async.commit_group;\n" ::);

        const unsigned* sA = sm + (kt & 3) * STAGE_U;
        const unsigned* sB = sA + 2048;
        const unsigned* pA = sA + (wm + g) * 16;
        const unsigned* pB = sB + (wn + g) * 16;

#pragma unroll
        for (int ks = 0; ks < 2; ++ks) {
            int c0 = (ks * 8 + tg) ^ swz;
            int c4 = (ks * 8 + tg + 4) ^ swz;
            unsigned af[4][4], bf[4][2];
#pragma unroll
            for (int i = 0; i < 4; ++i) {
                af[i][0] = pA[i * 256 + c0];
                af[i][1] = pA[i * 256 + 128 + c0];
                af[i][2] = pA[i * 256 + c4];
                af[i][3] = pA[i * 256 + 128 + c4];
            }
#pragma unroll
            for (int j = 0; j < 4; ++j) {
                bf[j][0] = pB[j * 128 + c0];
                bf[j][1] = pB[j * 128 + c4];
            }
#pragma unroll
            for (int i = 0; i < 4; ++i)
#pragma unroll
                for (int j = 0; j < 4; ++j)
                    mma_f16(acc[i][j], af[i], bf[j]);
        }
    }

#pragma unroll
    for (int i = 0; i < 4; ++i) {
        int r0 = m0 + wm + i * 16 + g;
#pragma unroll
        for (int j = 0; j < 4; ++j) {
            int c = n0 + wn + j * 8 + 2 * tg;
            float v0 = acc[i][j][0], v1 = acc[i][j][1];
            float v2 = acc[i][j][2], v3 = acc[i][j][3];
            if (Cinit) {
                if (cinit_half) {
                    const __half* Ch = (const __half*)Cinit;
                    float2 p0 = __half22float2(*(const __half2*)&Ch[(size_t)r0 * ldc + c]);
                    float2 p1 = __half22float2(*(const __half2*)&Ch[(size_t)(r0 + 8) * ldc + c]);
                    v0 += p0.x; v1 += p0.y; v2 += p1.x; v3 += p1.y;
                } else {
                    const float* Cf = (const float*)Cinit;
                    float2 p0 = *(const float2*)&Cf[(size_t)r0 * ldc + c];
                    float2 p1 = *(const float2*)&Cf[(size_t)(r0 + 8) * ldc + c];
                    v0 += p0.x; v1 += p0.y; v2 += p1.x; v3 += p1.y;
                }
            }
            if (bias) {
                float2 bb = *(const float2*)&bias[c];
                v0 += bb.x; v1 += bb.y; v2 += bb.x; v3 += bb.y;
            }
            if (out_half) {
                __half* Ch = (__half*)C;
                *(__half2*)&Ch[(size_t)r0 * ldc + c]       = __floats2half2_rn(v0, v1);
                *(__half2*)&Ch[(size_t)(r0 + 8) * ldc + c] = __floats2half2_rn(v2, v3);
            } else {
                *(float2*)&C[(size_t)r0 * ldc + c]       = make_float2(v0, v1);
                *(float2*)&C[(size_t)(r0 + 8) * ldc + c] = make_float2(v2, v3);
            }
        }
    }
}

// ---------------------------------------------------------------------------
// MHA core per (l, b): both heads per block. fp16 smem (raw copy loader),
// row stride 68 half2 = 272B (16B aligned; conflict-free LDS.128).
// ---------------------------------------------------------------------------
#define AH2 68   // row stride in half2 units (272 bytes)

__global__ __launch_bounds__(768)
void attn_kernel(const __half* __restrict__ qkv, const float* __restrict__ mask,
                 __half* __restrict__ att) {
    cudaGridDependencySynchronize();
    int bid = blockIdx.x;
    int b = bid & 63;
    int l = bid >> 6;

    __shared__ __align__(16) __half2 qs[RR * AH2];
    __shared__ __align__(16) __half2 ks[32 * AH2];   // rows 24..31 zeroed
    __shared__ __align__(16) __half2 vs[RR * AH2];
    __shared__ float ps[RR * 32];

    int tid = threadIdx.x;
    // raw copy: 24 rows x 48 float4 (each = 4 half2); no conversion
    for (int idx = tid; idx < RR * 48; idx += 768) {
        int s = idx / 48;
        int u = idx % 48;
        float4 raw = ((const float4*)(qkv + ((size_t)(l * RR + s) * BB + b) * 384))[u];
        int seg = u >> 4;              // 0=q, 1=k, 2=v
        int w4 = (u & 15) * 4;         // half2 offset within row
        __half2* dst = (seg == 0) ? &qs[s * AH2 + w4]
                     : (seg == 1) ? &ks[s * AH2 + w4]
                                  : &vs[s * AH2 + w4];
        *(float4*)dst = raw;
    }
    for (int idx = tid; idx < 8 * 17; idx += 768) {   // zero ks pad rows
        int s = RR + idx / 17, u = (idx % 17) * 4;
        *(float4*)&ks[s * AH2 + u] = make_float4(0.f, 0.f, 0.f, 0.f);
    }
    __syncthreads();

    int w = tid >> 5, lane = tid & 31;
    if (w >= RR) return;
    int r = w;
    float mk = (lane < RR) ? mask[r * RR + lane] : 0.f;

#pragma unroll
    for (int h = 0; h < 2; ++h) {
        int hb = h * 32;   // half2 offset of head within row
        // scores: lane j computes q[r]·k[j] over 64 dims (8 LDS.128 each side)
        float a0 = 0.f, a1 = 0.f;
#pragma unroll
        for (int d8 = 0; d8 < 8; ++d8) {
            float4 qraw = *(const float4*)&qs[r * AH2 + hb + d8 * 4];
            float4 kraw = *(const float4*)&ks[lane * AH2 + hb + d8 * 4];
            const __half2* qh = (const __half2*)&qraw;
            const __half2* kh = (const __half2*)&kraw;
#pragma unroll
            for (int t = 0; t < 4; ++t) {
                float2 qf = __half22float2(qh[t]);
                float2 kf = __half22float2(kh[t]);
                a0 = fmaf(qf.x, kf.x, a0);
                a1 = fmaf(qf.y, kf.y, a1);
            }
        }
        float sc = a0 + a1;
        float sco = (lane < RR) ? sc * 0.125f + mk : -INFINITY;

        float mx = sco;
#pragma unroll
        for (int off = 16; off; off >>= 1)
            mx = fmaxf(mx, __shfl_xor_sync(0xffffffffu, mx, off));
        float e = __expf(sco - mx);
        float sum = e;
#pragma unroll
        for (int off = 16; off; off >>= 1)
            sum += __shfl_xor_sync(0xffffffffu, sum, off);
        ps[r * 32 + lane] = e / sum;
        __syncwarp();

        // PV: lane handles dims (2*lane, 2*lane+1) via one half2 per step
        float acc0 = 0.f, acc1 = 0.f;
#pragma unroll
        for (int s = 0; s < RR; ++s) {
            float p = ps[r * 32 + s];
            float2 v01 = __half22float2(vs[s * AH2 + hb + lane]);
            acc0 = fmaf(p, v01.x, acc0);
            acc1 = fmaf(p, v01.y, acc1);
        }
        int mo = ((l * RR + r) * BB + b) * EMB + h * 64;
        *(__half2*)&att[mo + 2 * lane] = __floats2half2_rn(acc0, acc1);
        __syncwarp();
    }
}

// ---------------------------------------------------------------------------
// Gate / state update / outputs. g, g2 fp16 (g2 optional split-K partial).
// One item per thread; launch with 384 blocks x 256 (M1*64 = 98304 threads).
// ---------------------------------------------------------------------------
__global__ __launch_bounds__(256)
void gate_kernel(const __half* __restrict__ g,
                 const __half* __restrict__ g2,
                 const __half* __restrict__ hin,
                 __half* __restrict__ hout,
                 const float* __restrict__ Bias,
                 float* __restrict__ out_all,
                 float* __restrict__ out_col,
                 float* __restrict__ out_row,
                 int s) {
    cudaGridDependencySynchronize();
    int idx = blockIdx.x * 256 + threadIdx.x;
    int c = idx & 63;
    int m = idx >> 6;
    int b = m & 63;
    int r = m >> 6;

    float4 q[6];
    {
        const __half2* Gh = (const __half2*)(g + (size_t)m * 1536);
#pragma unroll
        for (int t = 0; t < 6; ++t) {
            float2 a = __half22float2(Gh[t * 128 + 2 * c]);
            float2 bb = __half22float2(Gh[t * 128 + 2 * c + 1]);
            q[t] = make_float4(a.x, a.y, bb.x, bb.y);
        }
    }
    if (g2) {
        const __half2* Gh = (const __half2*)(g2 + (size_t)m * 1536);
#pragma unroll
        for (int t = 0; t < 6; ++t) {
            float2 a = __half22float2(Gh[t * 128 + 2 * c]);
            float2 bb = __half22float2(Gh[t * 128 + 2 * c + 1]);
            q[t].x += a.x; q[t].y += a.y; q[t].z += bb.x; q[t].w += bb.y;
        }
    }
    if (r <= s && s < RR) {
        const float4* B4 = (const float4*)Bias;
#pragma unroll
        for (int t = 0; t < 6; ++t) {
            float4 bb = B4[c + t * 64];
            q[t].x += bb.x; q[t].y += bb.y; q[t].z += bb.z; q[t].w += bb.w;
        }
    }
    float* qa = (float*)q;

    const __half2* HR = (const __half2*)(hin + (size_t)m * 512) + c * 2;
    const __half2* HC = (const __half2*)(hin + (size_t)m * 512 + 256) + c * 2;
    float2 hr01 = __half22float2(HR[0]);
    float2 hr23 = __half22float2(HR[1]);
    float2 hc01 = __half22float2(HC[0]);
    float2 hc23 = __half22float2(HC[1]);
    float hrp[4] = {hr01.x, hr01.y, hr23.x, hr23.y};
    float hcp[4] = {hc01.x, hc01.y, hc23.x, hc23.y};

    float hr[4], hc[4];
#pragma unroll
    for (int t = 0; t < 4; ++t) {
        float ug_r = sigf(qa[t]);
        float og_r = sigf(qa[4 + t]);
        float ug_c = sigf(qa[8 + t]);
        float og_c = sigf(qa[12 + t]);
        float ig_r = tanha(qa[16 + t]);
        float ig_c = tanha(qa[20 + t]);
        hr[t] = tanha((1.f - ug_r) * hrp[t] + ug_r * ig_r) * og_r;
        hc[t] = tanha((1.f - ug_c) * hcp[t] + ug_c * ig_c) * og_c;
    }
    float4 hr4 = make_float4(hr[0], hr[1], hr[2], hr[3]);
    float4 hc4 = make_float4(hc[0], hc[1], hc[2], hc[3]);

    int r2 = (r + 1) % RR;
    int mc = r2 * BB + b;
    __half2* OR = (__half2*)(hout + (size_t)m * 512) + c * 2;
    __half2* OC = (__half2*)(hout + (size_t)mc * 512 + 256) + c * 2;
    OR[0] = __floats2half2_rn(hr[0], hr[1]);
    OR[1] = __floats2half2_rn(hr[2], hr[3]);
    OC[0] = __floats2half2_rn(hc[0], hc[1]);
    OC[1] = __floats2half2_rn(hc[2], hc[3]);

    float* ob = out_all + ((size_t)m * LSTEPS + s) * 512;
    __stcs((float4*)ob + c, hr4);
    __stcs((float4*)(ob + 256) + c, hc4);

    if (s >= OO - 1) {
        int t2 = s - (OO - 1);
        if (r == t2)      ((float4*)(out_row + (size_t)(b * RR + t2) * HH))[c] = hr4;
        if (r == RR - 1)  ((float4*)(out_col + (size_t)(b * OO + t2) * HH))[c] = hc4;
    }
}

// ---------------------------------------------------------------------------
// Launch
// ---------------------------------------------------------------------------
extern "C" void kernel_launch(void* const* d_in, const int* in_sizes, int n_in,
                              void* d_out, int out_size) {
    const float* input = (const float*)d_in[0];
    const float* mask  = (const float*)d_in[1];
    const float* W     = (const float*)d_in[2];
    const float* Bias  = (const float*)d_in[3];
    const float* inw   = (const float*)d_in[4];
    const float* inb   = (const float*)d_in[5];
    const float* outw  = (const float*)d_in[6];
    const float* outb  = (const float*)d_in[7];
    float* out = (float*)d_out;

    __half *xy, *qkv, *att, *pre, *ht, *g, *Wt, *inwt, *outwt;
    cudaGetSymbolAddress((void**)&xy,    d_xy);
    cudaGetSymbolAddress((void**)&qkv,   d_qkv);
    cudaGetSymbolAddress((void**)&att,   d_att);
    cudaGetSymbolAddress((void**)&pre,   d_pre);
    cudaGetSymbolAddress((void**)&ht,    d_ht);
    cudaGetSymbolAddress((void**)&g,     d_g);
    cudaGetSymbolAddress((void**)&Wt,    d_Wt);
    cudaGetSymbolAddress((void**)&inwt,  d_inwt);
    cudaGetSymbolAddress((void**)&outwt, d_outwt);

    cudaFuncSetAttribute(gemm_mma, cudaFuncAttributeMaxDynamicSharedMemorySize, 65536);
    const int SMEMB = 65536;

    // 0) one-time weight conversion to fp16
    cvt_all_kernel<<<(W4 + IW4 + OW4 + 255) / 256, 256>>>(W, Wt, inw, inwt, outw, outwt);

    // 1) x (fp16)
    build_x_kernel<<<(MALL * 32 + 255) / 256, 256>>>(input, xy);

    // 2) qkv = x @ in_proj_wᵀ + b  (fp16 out)
    gemm_mma<<<dim3(3, MALL / 128), 256, SMEMB>>>(xy, 256, inwt, EMB, inb,
                                                  nullptr, 0,
                                                  (float*)qkv, 384, EMB, 1, 0);

    // 3) attention (fp16 in/out, both heads per block)
    attn_kernel<<<LSTEPS * BB, 768>>>(qkv, mask, att);

    // 4) y = att @ out_proj_wᵀ + b -> xy[:,128:256] (fp16 out)
    gemm_mma<<<dim3(1, MALL / 128), 256, SMEMB>>>(att, EMB, outwt, EMB, outb,
                                                  nullptr, 0,
                                                  (float*)(xy + 128), 256, EMB, 1, 0);

    // 5) pre = [x|y] @ W[:, 512:768]ᵀ (fp16 out)
    gemm_mma<<<dim3(12, MALL / 128), 256, SMEMB>>>(xy, 256, Wt + 512, 768, nullptr,
                                                   nullptr, 0,
                                                   (float*)pre, 1536, 256, 1, 0);

    // 6) zero initial state (buffer 0)
    cudaMemsetAsync(ht, 0, (size_t)M1 * 512 * sizeof(__half));

    // PDL launch configs for the scan loop
    cudaLaunchAttribute pdlAttr[1];
    pdlAttr[0].id = cudaLaunchAttributeProgrammaticStreamSerialization;
    pdlAttr[0].val.programmaticStreamSerializationAllowed = 1;

    cudaLaunchConfig_t cfgGemm = {};
    cfgGemm.gridDim  = dim3(12, 12, 2);      // split-K = 2
    cfgGemm.blockDim = dim3(256);
    cfgGemm.dynamicSmemBytes = SMEMB;
    cfgGemm.stream = 0;
    cfgGemm.attrs = pdlAttr;
    cfgGemm.numAttrs = 1;

    cudaLaunchConfig_t cfgGate = {};
    cfgGate.gridDim  = dim3(384);
    cfgGate.blockDim = dim3(256);
    cfgGate.dynamicSmemBytes = 0;
    cfgGate.stream = 0;
    cfgGate.attrs = pdlAttr;
    cfgGate.numAttrs = 1;

    float* out_col = out + OUT_ALL_ELEMS;
    float* out_row = out + OUT_ALL_ELEMS + HID_ELEMS;
    __half* g1 = g + (size_t)M1 * 1536;

    // 7) sequential scan; s=0 skips the GEMM (h == 0 -> g == pre[0], fp16)
    gate_kernel<<<384, 256>>>(pre, (const __half*)nullptr, ht,
                              ht + (size_t)M1 * 512, Bias,
                              out, out_col, out_row, 0);
    for (int s = 1; s < LSTEPS; ++s) {
        const __half* hin = ht + (size_t)(s & 1) * M1 * 512;
        __half* hout      = ht + (size_t)((s + 1) & 1) * M1 * 512;
        cudaLaunchKernelEx(&cfgGemm, gemm_mma,
                           hin, 512, (const __half*)Wt, 768,
                           (const float*)nullptr,
                           (const void*)(pre + (size_t)s * M1 * 1536), 1,
                           (float*)g, 1536, 256, 1, 256);
        cudaLaunchKernelEx(&cfgGate, gate_kernel,
                           (const __half*)g, (const __half*)g1, hin, hout,
                           Bias, out, out_col, out_row, s);
    }
}